// round 1
// baseline (speedup 1.0000x reference)
#include <cuda_runtime.h>
#include <math.h>

// Problem constants (fixed shapes per dataset)
#define HD   4096   // hidden size
#define IS   2048   // routed expert intermediate
#define NE   16     // experts
#define NK   4      // top-k
#define SIW  2048   // shared expert intermediate
#define TMAX 4096   // max tokens (2*2048)

#define BM 128
#define BN 128
#define BK 8

// ---------------- static device scratch (no allocations allowed) ----------------
__device__ int   d_cnt[NE];
__device__ int   d_tok[NE * TMAX];
__device__ float d_wgt[NE * TMAX];
__device__ float d_bufG[(size_t)NE * TMAX * IS];   // routed gate proj, then z in-place
__device__ float d_bufU[(size_t)NE * TMAX * IS];   // routed up proj
__device__ float d_sG[(size_t)TMAX * SIW];         // shared gate, then z in-place
__device__ float d_sU[(size_t)TMAX * SIW];         // shared up

__device__ __forceinline__ float* bufptr(int s) {
    switch (s) {
        case 0:  return d_bufG;
        case 1:  return d_bufU;
        case 2:  return d_sG;
        default: return d_sU;
    }
}

// ---------------- router ----------------
__global__ void zero_cnt_kernel() {
    if (threadIdx.x < NE) d_cnt[threadIdx.x] = 0;
}

__global__ void router_kernel(const float* __restrict__ x,
                              const float* __restrict__ gw,
                              const float* __restrict__ bias) {
    __shared__ float sx[HD];
    __shared__ float sc[NE];
    int t = blockIdx.x;
    const float4* xr = (const float4*)(x + (size_t)t * HD);
    for (int i = threadIdx.x; i < HD / 4; i += blockDim.x)
        ((float4*)sx)[i] = xr[i];
    __syncthreads();

    int warp = threadIdx.x >> 5, lane = threadIdx.x & 31;
    int nwarp = blockDim.x >> 5;
    for (int e = warp; e < NE; e += nwarp) {
        const float* w = gw + (size_t)e * HD;
        float s = 0.f;
        for (int i = lane; i < HD; i += 32) s = fmaf(sx[i], w[i], s);
        #pragma unroll
        for (int o = 16; o > 0; o >>= 1) s += __shfl_xor_sync(0xffffffffu, s, o);
        if (lane == 0) sc[e] = 1.f / (1.f + expf(-s)) + bias[e];
    }
    __syncthreads();

    if (threadIdx.x == 0) {
        float v[NE];
        #pragma unroll
        for (int e = 0; e < NE; e++) v[e] = sc[e];
        int   idx[NK];
        float wv[NK];
        float sum = 0.f;
        #pragma unroll
        for (int k = 0; k < NK; k++) {
            int bi = 0; float bv = -1e30f;
            #pragma unroll
            for (int e = 0; e < NE; e++) if (v[e] > bv) { bv = v[e]; bi = e; }
            idx[k] = bi; wv[k] = bv; v[bi] = -1e30f; sum += bv;
        }
        float inv = 1.f / (sum + 1e-20f);
        #pragma unroll
        for (int k = 0; k < NK; k++) {
            int e   = idx[k];
            int pos = atomicAdd(&d_cnt[e], 1);
            d_tok[e * TMAX + pos] = t;
            d_wgt[e * TMAX + pos] = wv[k] * inv;
        }
    }
}

// ---------------- SGEMM: C[M,N] = A[M,K] * B[N,K]^T ----------------
// MODE 0: plain (shared expert).  M passed in.
// MODE 1: gather A rows from X via per-expert token list; C = per-expert buffer.
// MODE 2: A = per-expert buffer; scatter C rows to out via token list with atomicAdd.
template<int MODE>
__global__ __launch_bounds__(256, 2)
void sgemm_kernel(const float* __restrict__ Aext,
                  const float* __restrict__ Bext,
                  float* __restrict__ Cext,
                  int aSel, int cSel,
                  int M, int K, int N,
                  long long sB, long long sAC) {
    int e = blockIdx.z;
    const int* tok = d_tok + e * TMAX;
    if (MODE != 0) M = d_cnt[e];
    if ((int)blockIdx.y * BM >= M) return;

    const float* A = (aSel >= 0) ? bufptr(aSel) : Aext;
    float*       C = (cSel >= 0) ? bufptr(cSel) : Cext;
    const float* B = Bext + (size_t)e * sB;
    if (MODE == 1) C += (size_t)e * sAC;
    if (MODE == 2) A += (size_t)e * sAC;

    __shared__ float As[BK][BM];
    __shared__ float Bs[BK][BN];

    int tid  = threadIdx.x;
    int lrow = tid >> 1;           // 0..127
    int lcol = (tid & 1) << 2;     // 0 or 4
    int ty   = tid >> 4;           // 0..15
    int tx   = tid & 15;           // 0..15

    int  gRow   = blockIdx.y * BM + lrow;
    bool avalid = gRow < M;
    const float* aptr;
    if (MODE == 1) {
        int r = avalid ? tok[gRow] : 0;
        aptr  = A + (size_t)r * K;
    } else {
        aptr  = A + (size_t)(avalid ? gRow : 0) * K;
    }
    const float* bptr = B + (size_t)(blockIdx.x * BN + lrow) * K;

    float acc[8][8];
    #pragma unroll
    for (int i = 0; i < 8; i++)
        #pragma unroll
        for (int j = 0; j < 8; j++) acc[i][j] = 0.f;

    float4 aR, bR;
    aR = avalid ? *(const float4*)(aptr + lcol) : make_float4(0.f, 0.f, 0.f, 0.f);
    bR = *(const float4*)(bptr + lcol);
    As[lcol + 0][lrow] = aR.x; As[lcol + 1][lrow] = aR.y;
    As[lcol + 2][lrow] = aR.z; As[lcol + 3][lrow] = aR.w;
    Bs[lcol + 0][lrow] = bR.x; Bs[lcol + 1][lrow] = bR.y;
    Bs[lcol + 2][lrow] = bR.z; Bs[lcol + 3][lrow] = bR.w;
    __syncthreads();

    int ntiles = K / BK;
    for (int tI = 0; tI < ntiles; tI++) {
        if (tI + 1 < ntiles) {
            int kn = (tI + 1) * BK + lcol;
            aR = avalid ? *(const float4*)(aptr + kn) : make_float4(0.f, 0.f, 0.f, 0.f);
            bR = *(const float4*)(bptr + kn);
        }
        #pragma unroll
        for (int kk = 0; kk < BK; kk++) {
            float a[8], b[8];
            *(float4*)&a[0] = *(const float4*)&As[kk][ty * 8];
            *(float4*)&a[4] = *(const float4*)&As[kk][ty * 8 + 4];
            *(float4*)&b[0] = *(const float4*)&Bs[kk][tx * 8];
            *(float4*)&b[4] = *(const float4*)&Bs[kk][tx * 8 + 4];
            #pragma unroll
            for (int i = 0; i < 8; i++)
                #pragma unroll
                for (int j = 0; j < 8; j++)
                    acc[i][j] = fmaf(a[i], b[j], acc[i][j]);
        }
        __syncthreads();
        if (tI + 1 < ntiles) {
            As[lcol + 0][lrow] = aR.x; As[lcol + 1][lrow] = aR.y;
            As[lcol + 2][lrow] = aR.z; As[lcol + 3][lrow] = aR.w;
            Bs[lcol + 0][lrow] = bR.x; Bs[lcol + 1][lrow] = bR.y;
            Bs[lcol + 2][lrow] = bR.z; Bs[lcol + 3][lrow] = bR.w;
            __syncthreads();
        }
    }

    int crow0 = blockIdx.y * BM + ty * 8;
    int ccol0 = blockIdx.x * BN + tx * 8;
    #pragma unroll
    for (int i = 0; i < 8; i++) {
        int r = crow0 + i;
        if (r < M) {
            if (MODE == 2) {
                int trow  = tok[r];
                float* cp = C + (size_t)trow * N + ccol0;
                #pragma unroll
                for (int j = 0; j < 8; j++) atomicAdd(cp + j, acc[i][j]);
            } else {
                float* cp = C + (size_t)r * N + ccol0;
                *(float4*)cp       = make_float4(acc[i][0], acc[i][1], acc[i][2], acc[i][3]);
                *(float4*)(cp + 4) = make_float4(acc[i][4], acc[i][5], acc[i][6], acc[i][7]);
            }
        }
    }
}

// ---------------- activation kernels ----------------
__device__ __forceinline__ float silu_f(float v) {
    return v / (1.f + expf(-v));
}

__global__ void routed_act_kernel() {
    int e   = blockIdx.y;
    int row = blockIdx.x;
    if (row >= d_cnt[e]) return;
    float  w    = d_wgt[e * TMAX + row];
    size_t base = ((size_t)e * TMAX + row) * IS;
    float4*       g4 = (float4*)(d_bufG + base);
    const float4* u4 = (const float4*)(d_bufU + base);
    for (int i = threadIdx.x; i < IS / 4; i += blockDim.x) {
        float4 g = g4[i], u = u4[i], z;
        z.x = silu_f(g.x) * u.x * w;
        z.y = silu_f(g.y) * u.y * w;
        z.z = silu_f(g.z) * u.z * w;
        z.w = silu_f(g.w) * u.w * w;
        g4[i] = z;
    }
}

__global__ void shared_act_kernel() {
    int    row  = blockIdx.x;
    size_t base = (size_t)row * SIW;
    float4*       g4 = (float4*)(d_sG + base);
    const float4* u4 = (const float4*)(d_sU + base);
    for (int i = threadIdx.x; i < SIW / 4; i += blockDim.x) {
        float4 g = g4[i], u = u4[i], z;
        z.x = silu_f(g.x) * u.x;
        z.y = silu_f(g.y) * u.y;
        z.z = silu_f(g.z) * u.z;
        z.w = silu_f(g.w) * u.w;
        g4[i] = z;
    }
}

// ---------------- launch ----------------
extern "C" void kernel_launch(void* const* d_in, const int* in_sizes, int n_in,
                              void* d_out, int out_size) {
    const float* x    = (const float*)d_in[0];   // [2,2048,H]
    const float* gw   = (const float*)d_in[1];   // [E,H]
    const float* bias = (const float*)d_in[2];   // [E]
    const float* Wg   = (const float*)d_in[3];   // [E,I,H]
    const float* Wu   = (const float*)d_in[4];   // [E,I,H]
    const float* Wd   = (const float*)d_in[5];   // [E,H,I]
    const float* Sg   = (const float*)d_in[6];   // [SI,H]
    const float* Su   = (const float*)d_in[7];   // [SI,H]
    const float* Sd   = (const float*)d_in[8];   // [H,SI]
    float* out = (float*)d_out;

    int Tn = in_sizes[0] / HD;          // 4096 tokens
    int mt = (Tn + BM - 1) / BM;

    zero_cnt_kernel<<<1, 32>>>();
    router_kernel<<<Tn, 128>>>(x, gw, bias);

    // shared expert: gs = X @ Sg^T, us = X @ Su^T, zs = silu(gs)*us, out = zs @ Sd^T
    sgemm_kernel<0><<<dim3(SIW / BN, mt, 1), 256>>>(x, Sg, nullptr, -1, 2, Tn, HD, SIW, 0, 0);
    sgemm_kernel<0><<<dim3(SIW / BN, mt, 1), 256>>>(x, Su, nullptr, -1, 3, Tn, HD, SIW, 0, 0);
    shared_act_kernel<<<Tn, 256>>>();
    sgemm_kernel<0><<<dim3(HD / BN, mt, 1), 256>>>(nullptr, Sd, out, 2, -1, Tn, SIW, HD, 0, 0);

    // routed experts (sparse): gather rows of X per expert, gated MLP, scatter-add to out
    sgemm_kernel<1><<<dim3(IS / BN, mt, NE), 256>>>(x, Wg, nullptr, -1, 0, 0, HD, IS,
                                                    (long long)IS * HD, (long long)TMAX * IS);
    sgemm_kernel<1><<<dim3(IS / BN, mt, NE), 256>>>(x, Wu, nullptr, -1, 1, 0, HD, IS,
                                                    (long long)IS * HD, (long long)TMAX * IS);
    routed_act_kernel<<<dim3(Tn, NE), 256>>>();
    sgemm_kernel<2><<<dim3(HD / BN, mt, NE), 256>>>(nullptr, Wd, out, 0, -1, 0, IS, HD,
                                                    (long long)HD * IS, (long long)TMAX * IS);
    (void)n_in; (void)out_size;
}

// round 2
// speedup vs baseline: 2.5097x; 2.5097x over previous
#include <cuda_runtime.h>
#include <math.h>

// Problem constants (fixed shapes per dataset)
#define HD   4096   // hidden size
#define IS   2048   // routed expert intermediate
#define NE   16     // experts
#define NK   4      // top-k
#define SIW  2048   // shared expert intermediate
#define TMAX 4096   // max tokens (2*2048)

#define BM   128
#define BN   128
#define BKT  16     // K elements per pipeline stage
#define LSTR 20     // padded smem row stride in floats (16 + 4) -> conflict-free

// ---------------- static device scratch (no allocations allowed) ----------------
__device__ int   d_cnt[NE];
__device__ int   d_tok[NE * TMAX];
__device__ float d_wgt[NE * TMAX];
__device__ float d_bufG[(size_t)NE * TMAX * IS];   // routed gate proj, then z in-place
__device__ float d_bufU[(size_t)NE * TMAX * IS];   // routed up proj
__device__ float d_sG[(size_t)TMAX * SIW];         // shared gate, then z in-place
__device__ float d_sU[(size_t)TMAX * SIW];         // shared up

__device__ __forceinline__ float* bufptr(int s) {
    switch (s) {
        case 0:  return d_bufG;
        case 1:  return d_bufU;
        case 2:  return d_sG;
        default: return d_sU;
    }
}

// ---------------- helpers ----------------
__device__ __forceinline__ unsigned su32(const void* p) {
    return (unsigned)__cvta_generic_to_shared(p);
}
__device__ __forceinline__ unsigned f2tf32(float f) {
    unsigned r;
    asm("cvt.rna.tf32.f32 %0, %1;" : "=r"(r) : "f"(f));
    return r;
}
#define CPA16(dst, src) \
    asm volatile("cp.async.cg.shared.global [%0], [%1], 16;" :: "r"(dst), "l"(src))
#define CPA_COMMIT() asm volatile("cp.async.commit_group;")
#define CPA_WAIT(n)  asm volatile("cp.async.wait_group %0;" :: "n"(n))

__device__ __forceinline__ void mma_tf32(float* d, const unsigned* a, unsigned b0, unsigned b1) {
    asm volatile(
        "mma.sync.aligned.m16n8k8.row.col.f32.tf32.tf32.f32 "
        "{%0,%1,%2,%3}, {%4,%5,%6,%7}, {%8,%9}, {%0,%1,%2,%3};"
        : "+f"(d[0]), "+f"(d[1]), "+f"(d[2]), "+f"(d[3])
        : "r"(a[0]), "r"(a[1]), "r"(a[2]), "r"(a[3]), "r"(b0), "r"(b1));
}

// ---------------- router ----------------
__global__ void zero_cnt_kernel() {
    if (threadIdx.x < NE) d_cnt[threadIdx.x] = 0;
}

__global__ void router_kernel(const float* __restrict__ x,
                              const float* __restrict__ gw,
                              const float* __restrict__ bias) {
    __shared__ float sx[HD];
    __shared__ float sc[NE];
    int t = blockIdx.x;
    const float4* xr = (const float4*)(x + (size_t)t * HD);
    for (int i = threadIdx.x; i < HD / 4; i += blockDim.x)
        ((float4*)sx)[i] = xr[i];
    __syncthreads();

    int warp = threadIdx.x >> 5, lane = threadIdx.x & 31;
    int nwarp = blockDim.x >> 5;
    for (int e = warp; e < NE; e += nwarp) {
        const float* w = gw + (size_t)e * HD;
        float s = 0.f;
        for (int i = lane; i < HD; i += 32) s = fmaf(sx[i], w[i], s);
        #pragma unroll
        for (int o = 16; o > 0; o >>= 1) s += __shfl_xor_sync(0xffffffffu, s, o);
        if (lane == 0) sc[e] = 1.f / (1.f + expf(-s)) + bias[e];
    }
    __syncthreads();

    if (threadIdx.x == 0) {
        float v[NE];
        #pragma unroll
        for (int e = 0; e < NE; e++) v[e] = sc[e];
        int   idx[NK];
        float wv[NK];
        float sum = 0.f;
        #pragma unroll
        for (int k = 0; k < NK; k++) {
            int bi = 0; float bv = -1e30f;
            #pragma unroll
            for (int e = 0; e < NE; e++) if (v[e] > bv) { bv = v[e]; bi = e; }
            idx[k] = bi; wv[k] = bv; v[bi] = -1e30f; sum += bv;
        }
        float inv = 1.f / (sum + 1e-20f);
        #pragma unroll
        for (int k = 0; k < NK; k++) {
            int e   = idx[k];
            int pos = atomicAdd(&d_cnt[e], 1);
            d_tok[e * TMAX + pos] = t;
            d_wgt[e * TMAX + pos] = wv[k] * inv;
        }
    }
}

// ---------------- tf32 tensor-core GEMM: C[M,N] = A[M,K] * B[N,K]^T ----------------
// MODE 0: plain (shared expert).  M passed in.
// MODE 1: gather A rows from X via per-expert token list; C = per-expert buffer.
// MODE 2: A = per-expert buffer; scatter C rows to out via token list with atomicAdd.
template<int MODE>
__global__ __launch_bounds__(256)
void gemm_tf32(const float* __restrict__ Aext,
               const float* __restrict__ Bext,
               float* __restrict__ Cext,
               int aSel, int cSel,
               int M, int K, int N,
               long long sB, long long sAC) {
    int e = blockIdx.z;
    const int* tok = d_tok + e * TMAX;
    if (MODE != 0) M = d_cnt[e];
    if ((int)blockIdx.y * BM >= M) return;

    const float* A = (aSel >= 0) ? bufptr(aSel) : Aext;
    float*       C = (cSel >= 0) ? bufptr(cSel) : Cext;
    const float* B = Bext + (size_t)e * sB;
    if (MODE == 1) C += (size_t)e * sAC;
    if (MODE == 2) A += (size_t)e * sAC;

    __shared__ float As[2][BM * LSTR];
    __shared__ float Bs[2][BN * LSTR];

    int tid  = threadIdx.x;
    int lane = tid & 31;
    int warp = tid >> 5;
    int wm   = warp & 3;      // 4 warps along M (32 rows each)
    int wn   = warp >> 2;     // 2 warps along N (64 cols each)

    // ---- loader mapping: each thread owns one row, 32 contiguous bytes ----
    int lrow = tid >> 1;              // 0..127
    int lcol = (tid & 1) * 8;         // float offset: 0 or 8
    int gRow = blockIdx.y * BM + lrow;
    const float* aRow;
    if (MODE == 1) {
        int r = (gRow < M) ? tok[gRow] : tok[0];
        aRow  = A + (size_t)r * K;
    } else {
        aRow  = A + (size_t)((gRow < M) ? gRow : 0) * K;
    }
    const float* bRow = B + (size_t)(blockIdx.x * BN + lrow) * K;

    unsigned sa0 = su32(&As[0][lrow * LSTR + lcol]);
    unsigned sa1 = su32(&As[1][lrow * LSTR + lcol]);
    unsigned sb0 = su32(&Bs[0][lrow * LSTR + lcol]);
    unsigned sb1 = su32(&Bs[1][lrow * LSTR + lcol]);

    float acc[2][8][4];
    #pragma unroll
    for (int i = 0; i < 2; i++)
        #pragma unroll
        for (int j = 0; j < 8; j++)
            #pragma unroll
            for (int q = 0; q < 4; q++) acc[i][j][q] = 0.f;

    int NT = K / BKT;

    // prologue: stage 0
    {
        const float* a = aRow + lcol;
        const float* b = bRow + lcol;
        CPA16(sa0,      a);
        CPA16(sa0 + 16, a + 4);
        CPA16(sb0,      b);
        CPA16(sb0 + 16, b + 4);
        CPA_COMMIT();
    }

    for (int s = 0; s < NT; s++) {
        if (s + 1 < NT) {
            int k0 = (s + 1) * BKT;
            unsigned da = ((s + 1) & 1) ? sa1 : sa0;
            unsigned db = ((s + 1) & 1) ? sb1 : sb0;
            const float* a = aRow + k0 + lcol;
            const float* b = bRow + k0 + lcol;
            CPA16(da,      a);
            CPA16(da + 16, a + 4);
            CPA16(db,      b);
            CPA16(db + 16, b + 4);
            CPA_COMMIT();
            CPA_WAIT(1);
        } else {
            CPA_WAIT(0);
        }
        __syncthreads();

        const float* as = As[s & 1];
        const float* bs = Bs[s & 1];

        #pragma unroll
        for (int ks = 0; ks < BKT; ks += 8) {
            unsigned a[2][4];
            #pragma unroll
            for (int i = 0; i < 2; i++) {
                int r0 = wm * 32 + i * 16 + (lane >> 2);
                int c0 = ks + (lane & 3);
                a[i][0] = f2tf32(as[r0 * LSTR + c0]);
                a[i][1] = f2tf32(as[(r0 + 8) * LSTR + c0]);
                a[i][2] = f2tf32(as[r0 * LSTR + c0 + 4]);
                a[i][3] = f2tf32(as[(r0 + 8) * LSTR + c0 + 4]);
            }
            #pragma unroll
            for (int j = 0; j < 8; j++) {
                int n0 = wn * 64 + j * 8 + (lane >> 2);
                int c0 = ks + (lane & 3);
                unsigned b0 = f2tf32(bs[n0 * LSTR + c0]);
                unsigned b1 = f2tf32(bs[n0 * LSTR + c0 + 4]);
                #pragma unroll
                for (int i = 0; i < 2; i++)
                    mma_tf32(acc[i][j], a[i], b0, b1);
            }
        }
        __syncthreads();
    }

    // ---- epilogue ----
    #pragma unroll
    for (int i = 0; i < 2; i++) {
        int r0 = blockIdx.y * BM + wm * 32 + i * 16 + (lane >> 2);
        #pragma unroll
        for (int j = 0; j < 8; j++) {
            int c0 = blockIdx.x * BN + wn * 64 + j * 8 + 2 * (lane & 3);
            if (MODE == 2) {
                if (r0 < M) {
                    int tr = tok[r0];
                    atomicAdd(C + (size_t)tr * N + c0,     acc[i][j][0]);
                    atomicAdd(C + (size_t)tr * N + c0 + 1, acc[i][j][1]);
                }
                if (r0 + 8 < M) {
                    int tr = tok[r0 + 8];
                    atomicAdd(C + (size_t)tr * N + c0,     acc[i][j][2]);
                    atomicAdd(C + (size_t)tr * N + c0 + 1, acc[i][j][3]);
                }
            } else {
                if (r0 < M) {
                    float2* cp = (float2*)(C + (size_t)r0 * N + c0);
                    *cp = make_float2(acc[i][j][0], acc[i][j][1]);
                }
                if (r0 + 8 < M) {
                    float2* cp = (float2*)(C + (size_t)(r0 + 8) * N + c0);
                    *cp = make_float2(acc[i][j][2], acc[i][j][3]);
                }
            }
        }
    }
}

// ---------------- activation kernels ----------------
__device__ __forceinline__ float silu_f(float v) {
    return v / (1.f + expf(-v));
}

__global__ void routed_act_kernel() {
    int e   = blockIdx.y;
    int row = blockIdx.x;
    if (row >= d_cnt[e]) return;
    float  w    = d_wgt[e * TMAX + row];
    size_t base = ((size_t)e * TMAX + row) * IS;
    float4*       g4 = (float4*)(d_bufG + base);
    const float4* u4 = (const float4*)(d_bufU + base);
    for (int i = threadIdx.x; i < IS / 4; i += blockDim.x) {
        float4 g = g4[i], u = u4[i], z;
        z.x = silu_f(g.x) * u.x * w;
        z.y = silu_f(g.y) * u.y * w;
        z.z = silu_f(g.z) * u.z * w;
        z.w = silu_f(g.w) * u.w * w;
        g4[i] = z;
    }
}

__global__ void shared_act_kernel() {
    int    row  = blockIdx.x;
    size_t base = (size_t)row * SIW;
    float4*       g4 = (float4*)(d_sG + base);
    const float4* u4 = (const float4*)(d_sU + base);
    for (int i = threadIdx.x; i < SIW / 4; i += blockDim.x) {
        float4 g = g4[i], u = u4[i], z;
        z.x = silu_f(g.x) * u.x;
        z.y = silu_f(g.y) * u.y;
        z.z = silu_f(g.z) * u.z;
        z.w = silu_f(g.w) * u.w;
        g4[i] = z;
    }
}

// ---------------- launch ----------------
extern "C" void kernel_launch(void* const* d_in, const int* in_sizes, int n_in,
                              void* d_out, int out_size) {
    const float* x    = (const float*)d_in[0];   // [2,2048,H]
    const float* gw   = (const float*)d_in[1];   // [E,H]
    const float* bias = (const float*)d_in[2];   // [E]
    const float* Wg   = (const float*)d_in[3];   // [E,I,H]
    const float* Wu   = (const float*)d_in[4];   // [E,I,H]
    const float* Wd   = (const float*)d_in[5];   // [E,H,I]
    const float* Sg   = (const float*)d_in[6];   // [SI,H]
    const float* Su   = (const float*)d_in[7];   // [SI,H]
    const float* Sd   = (const float*)d_in[8];   // [H,SI]
    float* out = (float*)d_out;

    int Tn = in_sizes[0] / HD;          // 4096 tokens
    int mt = (Tn + BM - 1) / BM;

    zero_cnt_kernel<<<1, 32>>>();
    router_kernel<<<Tn, 128>>>(x, gw, bias);

    // shared expert: gs = X @ Sg^T, us = X @ Su^T, zs = silu(gs)*us, out = zs @ Sd^T
    gemm_tf32<0><<<dim3(SIW / BN, mt, 1), 256>>>(x, Sg, nullptr, -1, 2, Tn, HD, SIW, 0, 0);
    gemm_tf32<0><<<dim3(SIW / BN, mt, 1), 256>>>(x, Su, nullptr, -1, 3, Tn, HD, SIW, 0, 0);
    shared_act_kernel<<<Tn, 256>>>();
    gemm_tf32<0><<<dim3(HD / BN, mt, 1), 256>>>(nullptr, Sd, out, 2, -1, Tn, SIW, HD, 0, 0);

    // routed experts (sparse): gather rows of X per expert, gated MLP, scatter-add to out
    gemm_tf32<1><<<dim3(IS / BN, mt, NE), 256>>>(x, Wg, nullptr, -1, 0, 0, HD, IS,
                                                 (long long)IS * HD, (long long)TMAX * IS);
    gemm_tf32<1><<<dim3(IS / BN, mt, NE), 256>>>(x, Wu, nullptr, -1, 1, 0, HD, IS,
                                                 (long long)IS * HD, (long long)TMAX * IS);
    routed_act_kernel<<<dim3(Tn, NE), 256>>>();
    gemm_tf32<2><<<dim3(HD / BN, mt, NE), 256>>>(nullptr, Wd, out, 0, -1, 0, IS, HD,
                                                 (long long)HD * IS, (long long)TMAX * IS);
    (void)n_in; (void)out_size;
}